// round 13
// baseline (speedup 1.0000x reference)
#include <cuda_runtime.h>
#include <math.h>

// BarycentricCoordinates: V=6000 x (R*A)=40 items, N=16 projections each.
// One thread per item.
//
// Bit-exactness model (validated R4-R12, rel_err == 0.0):
//  - einsum dot products (K=2): dot = __fmaf_rn(y,y', __fmul_rn(x,x'))
//  - all other elementwise ops: strict IEEE mul/sub/div/sqrt, no contraction.
//
// R13 = R12 (66.0us) with a cheaper nominate-then-verify hot loop:
//  - in-loop den/nA/nB CONTRACTED (FMUL+FFMA); the <=1-ulp sign uncertainty is
//    absorbed by 1e-5 weight-space margin gates on ALL three weights
//    (conservative: borderline pairs ACCEPTED, exact epilogue re-rejects).
//  - in-loop den==0 patch dropped (those pairs self-reject: gates == 0);
//    covered by a cold exact full scan whenever bestS stays INF.
//  - amax-form score; top-2 via sortable int keys (IMNMX chain, lat 4).
//  - exact epilogue identical to R12 (reference-bit formulas, IEEE divides).

#define MULF(a,b)   __fmul_rn((a),(b))
#define ADDF(a,b)   __fadd_rn((a),(b))
#define SUBF(a,b)   __fsub_rn((a),(b))
#define DIVF(a,b)   __fdiv_rn((a),(b))
#define DOT2(ax,ay,bx,by) __fmaf_rn((ay),(by), __fmul_rn((ax),(bx)))

#define KEY_SENTINEL 0x7FFFFFFFu

__global__ __launch_bounds__(128, 5)
void bc_kernel(const float* __restrict__ tmpl,
               const float* __restrict__ proj,
               float* __restrict__ out, int V)
{
    __shared__ float2 s_e[16][128];   // (ex, ey) exact bits
    __shared__ float2 s_d[16][128];   // (d00, d02) exact bits
    __shared__ float  s_dist[16][128];

    const int RA = 40;
    int tid = threadIdx.x;
    int gid = blockIdx.x * blockDim.x + tid;
    if (gid >= V * RA) return;        // exact grid: never diverges
    int v  = gid / RA;
    int ra = gid - v * RA;

    float tx = __ldg(tmpl + 2 * ra);
    float ty = __ldg(tmpl + 2 * ra + 1);

    float px[16], py[16];
    const float4* pp = (const float4*)(proj + (size_t)v * 32);
    #pragma unroll
    for (int k = 0; k < 8; k++) {
        float4 q = __ldg(pp + k);
        px[2*k]   = q.x; py[2*k]   = q.y;
        px[2*k+1] = q.z; py[2*k+1] = q.w;
    }

    // dist: strict IEEE; stash in smem for the epilogue, regs die after scan.
    float dist[16];
    #pragma unroll
    for (int i = 0; i < 16; i++) {
        float dx = SUBF(tx, px[i]), dy = SUBF(ty, py[i]);
        dist[i] = __fsqrt_rn(ADDF(MULF(dx,dx), MULF(dy,dy)));
        s_dist[i][tid] = dist[i];
    }

    // Stable two-min scan (branchless): closest (bi,bx,by) and 2nd (si)
    float bd = dist[0], bx = px[0], by = py[0], sd = INFINITY;
    int bi = 0, si = 0;
    #pragma unroll
    for (int i = 1; i < 16; i++) {
        bool lb = dist[i] < bd;
        bool ls = dist[i] < sd;
        sd = lb ? bd : (ls ? dist[i] : sd);
        si = lb ? bi : (ls ? i       : si);
        bd = lb ? dist[i] : bd;
        bx = lb ? px[i]   : bx;
        by = lb ? py[i]   : by;
        bi = lb ? i       : bi;
    }

    float v2x = SUBF(tx, bx), v2y = SUBF(ty, by);
    float ex[16], ey[16], d00[16], d02[16];
    #pragma unroll
    for (int i = 0; i < 16; i++) {
        ex[i]  = SUBF(px[i], bx);
        ey[i]  = SUBF(py[i], by);
        d00[i] = DOT2(ex[i], ey[i], ex[i], ey[i]);
        d02[i] = DOT2(ex[i], ey[i], v2x, v2y);
        s_e[i][tid] = make_float2(ex[i], ey[i]);
        s_d[i][tid] = make_float2(d00[i], d02[i]);
    }

    // ---- hot loop: contracted math + margin gates, int-key top-2 ----
    unsigned k1 = KEY_SENTINEL, k2 = KEY_SENTINEL;

    #pragma unroll
    for (int i = 0; i < 15; i++) {
        #pragma unroll
        for (int j = i + 1; j < 16; j++) {
            float d01 = DOT2(ex[i], ey[i], ex[j], ey[j]);
            // contracted (<=1 ulp off reference bits; margins absorb it)
            float den = __fmaf_rn(d00[i], d00[j], -__fmul_rn(d01, d01));
            float nA  = __fmaf_rn(d02[i], d00[j], -__fmul_rn(d01, d02[j]));
            float nB  = __fmaf_rn(d00[i], d02[j], -__fmul_rn(d01, d02[i]));
            float p0n  = SUBF(SUBF(den, nA), nB);   // ~ p0 * den
            float den2 = den * den;
            float e    = 1e-5f * den2;              // weight-space margin
            float gA = __fmaf_rn(nA,  den, e);      // pA > -1e-5
            float gB = __fmaf_rn(nB,  den, e);      // pB > -1e-5
            float gP = __fmaf_rn(p0n, den, e);      // p0 > -1e-5
            float m  = fminf(fminf(gA, gB), gP);
            float am = fmaxf(fabsf(nA), fabsf(nB));
            am = fmaxf(am, fabsf(p0n));
            float r;  asm("rcp.approx.f32 %0, %1;" : "=f"(r) : "f"(den2));
            float s  = (am * am) * r;               // >= 0 when valid
            unsigned key = (m > 0.0f)
                ? ((__float_as_uint(s) & 0xFFFFFF00u) | (unsigned)(i * 16 + j))
                : KEY_SENTINEL;
            unsigned mx = umax(k1, key);
            k1 = umin(k1, key);
            k2 = umin(k2, mx);
        }
    }

    // ---- exact epilogue: re-evaluate top-2 candidates bit-exactly ----
    float w0 = 0.f, w1 = 0.f, w2 = 0.f;
    int   o1 = si, o2 = si;
    float bestS = INFINITY;

    #pragma unroll
    for (int c = 0; c < 2; c++) {
        unsigned key = (c == 0) ? k1 : k2;
        if (key != KEY_SENTINEL) {
            int code = (int)(key & 255u);
            int ip = code >> 4, jp = code & 15;
            float2 eiv = s_e[ip][tid], ejv = s_e[jp][tid];
            float2 div = s_d[ip][tid], djv = s_d[jp][tid];
            float  di  = s_dist[ip][tid], dj = s_dist[jp][tid];
            float d01 = DOT2(eiv.x, eiv.y, ejv.x, ejv.y);       // exact bits
            float den = SUBF(MULF(div.x,djv.x), MULF(d01,d01));
            if (den == 0.0f) den = 1e-10f;
            float nA = SUBF(MULF(div.y,djv.x), MULF(d01,djv.y));
            float nB = SUBF(MULF(div.x,djv.y), MULF(d01,div.y));
            bool candx = (den > 0.0f) ? (nA > 0.0f && nB > 0.0f)
                                      : (nA < 0.0f && nB < 0.0f);
            if (candx) {
                float pA = DIVF(nA, den);                       // exact IEEE
                float pB = DIVF(nB, den);
                float m2  = fmaxf(MULF(pA,pA), MULF(pB,pB));
                float p0i = SUBF(SUBF(1.0f, pA), pB);
                float p0j = SUBF(SUBF(1.0f, pB), pA);
                float siS = (p0i > 0.f) ? fmaxf(MULF(p0i,p0i), m2) : INFINITY;
                float sjS = (p0j > 0.f) ? fmaxf(MULF(p0j,p0j), m2) : INFINITY;
                bool iFirst = (di <= dj);
                float sLow  = iFirst ? siS : sjS;
                float sHigh = iFirst ? sjS : siS;
                bool pickLow = (sLow <= sHigh);
                float s = pickLow ? sLow : sHigh;
                if (s < bestS) {
                    bestS = s;
                    bool icell = pickLow ? iFirst : !iFirst;
                    if (icell) { w0 = p0i; w1 = pA; w2 = pB; o1 = ip; o2 = jp; }
                    else       { w0 = p0j; w1 = pB; w2 = pA; o1 = jp; o2 = ip; }
                }
            }
        }
    }

    // ---- cold safety net: no candidate survived (incl. den==0-only items) ----
    if (!(bestS < INFINITY)) {
        #pragma unroll 1
        for (int ip = 0; ip < 15; ip++) {
            float2 eiv = s_e[ip][tid];
            float2 div = s_d[ip][tid];
            float  di  = s_dist[ip][tid];
            #pragma unroll 1
            for (int jp = ip + 1; jp < 16; jp++) {
                float2 ejv = s_e[jp][tid];
                float2 djv = s_d[jp][tid];
                float  dj  = s_dist[jp][tid];
                float d01 = DOT2(eiv.x, eiv.y, ejv.x, ejv.y);
                float den = SUBF(MULF(div.x,djv.x), MULF(d01,d01));
                if (den == 0.0f) den = 1e-10f;
                float nA = SUBF(MULF(div.y,djv.x), MULF(d01,djv.y));
                float nB = SUBF(MULF(div.x,djv.y), MULF(d01,div.y));
                bool candx = (den > 0.0f) ? (nA > 0.0f && nB > 0.0f)
                                          : (nA < 0.0f && nB < 0.0f);
                if (candx) {
                    float pA = DIVF(nA, den);
                    float pB = DIVF(nB, den);
                    float m2  = fmaxf(MULF(pA,pA), MULF(pB,pB));
                    float p0i = SUBF(SUBF(1.0f, pA), pB);
                    float p0j = SUBF(SUBF(1.0f, pB), pA);
                    float siS = (p0i > 0.f) ? fmaxf(MULF(p0i,p0i), m2) : INFINITY;
                    float sjS = (p0j > 0.f) ? fmaxf(MULF(p0j,p0j), m2) : INFINITY;
                    bool iFirst = (di <= dj);
                    float sLow  = iFirst ? siS : sjS;
                    float sHigh = iFirst ? sjS : siS;
                    bool pickLow = (sLow <= sHigh);
                    float s = pickLow ? sLow : sHigh;
                    if (s < bestS) {
                        bestS = s;
                        bool icell = pickLow ? iFirst : !iFirst;
                        if (icell) { w0 = p0i; w1 = pA; w2 = pB; o1 = ip; o2 = jp; }
                        else       { w0 = p0j; w1 = pB; w2 = pA; o1 = jp; o2 = ip; }
                    }
                }
            }
        }
        if (!(bestS < INFINITY)) {   // truly no valid pair: reference fallback
            w0 = 0.f; w1 = 0.f; w2 = 0.f; o1 = si; o2 = si;
        }
    }

    float* ow = out + (size_t)gid * 3;
    ow[0] = w0; ow[1] = w1; ow[2] = w2;
    float* oi = out + (size_t)V * RA * 3 + (size_t)gid * 3;
    oi[0] = (float)bi; oi[1] = (float)o1; oi[2] = (float)o2;
}

extern "C" void kernel_launch(void* const* d_in, const int* in_sizes, int n_in,
                              void* d_out, int out_size)
{
    const float* tmpl = (const float*)d_in[0];   // (5,8,2) = 80 floats
    const float* proj = (const float*)d_in[1];   // (V,16,2)
    int V = in_sizes[1] / 32;
    int total = V * 40;
    int threads = 128;
    int blocks = (total + threads - 1) / threads;
    bc_kernel<<<blocks, threads>>>(tmpl, proj, (float*)d_out, V);
}

// round 14
// speedup vs baseline: 1.5653x; 1.5653x over previous
#include <cuda_runtime.h>
#include <math.h>

// BarycentricCoordinates: V=6000 x (R*A)=40 items, N=16 projections each.
// One thread per item.
//
// Bit-exactness model (validated R4-R12, rel_err == 0.0):
//  - einsum dot products (K=2): dot = __fmaf_rn(y,y', __fmul_rn(x,x'))
//  - all other elementwise ops: strict IEEE mul/sub/div/sqrt, no contraction.
//
// R14 = R12 (66.0us, no spills) + ONE isolated change: the loop-carried top-2
// tracker switches from FSETP/SEL float compares (17-cyc carried chain) to
// sortable int keys (score high bits | pair code, IMNMX, 4-cyc chain).
// The hot-loop BODY math is untouched (exact-bit Gram chains + den==0 patch):
// those long chains throttle ptxas over-pipelining, which R7/R8/R9/R11/R13
// showed is the spill trigger. Exact epilogue + fallback identical to R12.

#define MULF(a,b)   __fmul_rn((a),(b))
#define ADDF(a,b)   __fadd_rn((a),(b))
#define SUBF(a,b)   __fsub_rn((a),(b))
#define DIVF(a,b)   __fdiv_rn((a),(b))
#define DOT2(ax,ay,bx,by) __fmaf_rn((ay),(by), __fmul_rn((ax),(bx)))

#define KEY_SENTINEL 0x7FFFFFFFu

__global__ __launch_bounds__(128, 5)
void bc_kernel(const float* __restrict__ tmpl,
               const float* __restrict__ proj,
               float* __restrict__ out, int V)
{
    __shared__ float2 s_e[16][128];   // (ex, ey)
    __shared__ float2 s_d[16][128];   // (d00, d02)
    __shared__ float  s_dist[16][128];

    const int RA = 40;
    int tid = threadIdx.x;
    int gid = blockIdx.x * blockDim.x + tid;
    if (gid >= V * RA) return;        // exact grid: never diverges
    int v  = gid / RA;
    int ra = gid - v * RA;

    float tx = __ldg(tmpl + 2 * ra);
    float ty = __ldg(tmpl + 2 * ra + 1);

    float px[16], py[16];
    const float4* pp = (const float4*)(proj + (size_t)v * 32);
    #pragma unroll
    for (int k = 0; k < 8; k++) {
        float4 q = __ldg(pp + k);
        px[2*k]   = q.x; py[2*k]   = q.y;
        px[2*k+1] = q.z; py[2*k+1] = q.w;
    }

    // dist: strict IEEE; stash in smem for the epilogue, regs die after scan.
    float dist[16];
    #pragma unroll
    for (int i = 0; i < 16; i++) {
        float dx = SUBF(tx, px[i]), dy = SUBF(ty, py[i]);
        dist[i] = __fsqrt_rn(ADDF(MULF(dx,dx), MULF(dy,dy)));
        s_dist[i][tid] = dist[i];
    }

    // Stable two-min scan (branchless): closest (bi,bx,by) and 2nd (si)
    float bd = dist[0], bx = px[0], by = py[0], sd = INFINITY;
    int bi = 0, si = 0;
    #pragma unroll
    for (int i = 1; i < 16; i++) {
        bool lb = dist[i] < bd;
        bool ls = dist[i] < sd;
        sd = lb ? bd : (ls ? dist[i] : sd);
        si = lb ? bi : (ls ? i       : si);
        bd = lb ? dist[i] : bd;
        bx = lb ? px[i]   : bx;
        by = lb ? py[i]   : by;
        bi = lb ? i       : bi;
    }

    float v2x = SUBF(tx, bx), v2y = SUBF(ty, by);
    float ex[16], ey[16], d00[16], d02[16];
    #pragma unroll
    for (int i = 0; i < 16; i++) {
        ex[i]  = SUBF(px[i], bx);
        ey[i]  = SUBF(py[i], by);
        d00[i] = DOT2(ex[i], ey[i], ex[i], ey[i]);
        d02[i] = DOT2(ex[i], ey[i], v2x, v2y);
        s_e[i][tid] = make_float2(ex[i], ey[i]);
        s_d[i][tid] = make_float2(d00[i], d02[i]);
    }

    // ---- approximate top-2 pair search: exact-bit body, int-key tracker ----
    unsigned k1 = KEY_SENTINEL, k2 = KEY_SENTINEL;

    #pragma unroll
    for (int i = 0; i < 15; i++) {
        #pragma unroll
        for (int j = i + 1; j < 16; j++) {
            float d01 = DOT2(ex[i], ey[i], ex[j], ey[j]);           // exact bits
            float den = SUBF(MULF(d00[i],d00[j]), MULF(d01,d01));   // exact bits
            den = (den == 0.0f) ? 1e-10f : den;
            float nA = SUBF(MULF(d02[i],d00[j]), MULF(d01,d02[j])); // exact bits
            float nB = SUBF(MULF(d00[i],d02[j]), MULF(d01,d02[i])); // exact bits
            float p0n  = SUBF(SUBF(den, nA), nB);     // ~ p0 * den (approx ok)
            float den2 = den * den;
            // sign-exact gates via products; conservative margin on p0
            float gA = nA * den;
            float gB = nB * den;
            float gP = __fmaf_rn(p0n, den, 1e-5f * den2);
            float m  = fminf(fminf(gA, gB), gP);
            float sNum = fmaxf(fmaxf(nA*nA, nB*nB), p0n*p0n);
            float r;
            asm("rcp.approx.f32 %0, %1;" : "=f"(r) : "f"(den2));    // MUFU pipe
            float s = sNum * r;                       // >= 0 when valid
            unsigned key = (m > 0.0f)
                ? ((__float_as_uint(s) & 0xFFFFFF00u) | (unsigned)(i * 16 + j))
                : KEY_SENTINEL;
            unsigned mx = umax(k1, key);              // IMNMX chain, lat 4
            k1 = umin(k1, key);
            k2 = umin(k2, mx);
        }
    }

    // ---- exact epilogue: re-evaluate top-2 candidates bit-exactly ----
    float w0 = 0.f, w1 = 0.f, w2 = 0.f;
    int   o1 = si, o2 = si;
    float bestS = INFINITY;

    #pragma unroll
    for (int c = 0; c < 2; c++) {
        unsigned key = (c == 0) ? k1 : k2;
        if (key != KEY_SENTINEL) {
            int code = (int)(key & 255u);
            int ip = code >> 4, jp = code & 15;
            float2 eiv = s_e[ip][tid], ejv = s_e[jp][tid];
            float2 div = s_d[ip][tid], djv = s_d[jp][tid];
            float  di  = s_dist[ip][tid], dj = s_dist[jp][tid];
            float d01 = DOT2(eiv.x, eiv.y, ejv.x, ejv.y);
            float den = SUBF(MULF(div.x,djv.x), MULF(d01,d01));
            if (den == 0.0f) den = 1e-10f;
            float nA = SUBF(MULF(div.y,djv.x), MULF(d01,djv.y));
            float nB = SUBF(MULF(div.x,djv.y), MULF(d01,div.y));
            bool candx = (den > 0.0f) ? (nA > 0.0f && nB > 0.0f)
                                      : (nA < 0.0f && nB < 0.0f);
            if (candx) {
                float pA = DIVF(nA, den);                 // exact IEEE divide
                float pB = DIVF(nB, den);
                float m2  = fmaxf(MULF(pA,pA), MULF(pB,pB));
                float p0i = SUBF(SUBF(1.0f, pA), pB);
                float p0j = SUBF(SUBF(1.0f, pB), pA);
                float siS = (p0i > 0.f) ? fmaxf(MULF(p0i,p0i), m2) : INFINITY;
                float sjS = (p0j > 0.f) ? fmaxf(MULF(p0j,p0j), m2) : INFINITY;
                bool iFirst = (di <= dj);
                float sLow  = iFirst ? siS : sjS;
                float sHigh = iFirst ? sjS : siS;
                bool pickLow = (sLow <= sHigh);
                float s = pickLow ? sLow : sHigh;
                if (s < bestS) {
                    bestS = s;
                    bool icell = pickLow ? iFirst : !iFirst;
                    if (icell) { w0 = p0i; w1 = pA; w2 = pB; o1 = ip; o2 = jp; }
                    else       { w0 = p0j; w1 = pB; w2 = pA; o1 = jp; o2 = ip; }
                }
            }
        }
    }

    if (!(bestS < INFINITY)) {   // no valid pair: reference fallback
        w0 = 0.f; w1 = 0.f; w2 = 0.f; o1 = si; o2 = si;
    }

    float* ow = out + (size_t)gid * 3;
    ow[0] = w0; ow[1] = w1; ow[2] = w2;
    float* oi = out + (size_t)V * RA * 3 + (size_t)gid * 3;
    oi[0] = (float)bi; oi[1] = (float)o1; oi[2] = (float)o2;
}

extern "C" void kernel_launch(void* const* d_in, const int* in_sizes, int n_in,
                              void* d_out, int out_size)
{
    const float* tmpl = (const float*)d_in[0];   // (5,8,2) = 80 floats
    const float* proj = (const float*)d_in[1];   // (V,16,2)
    int V = in_sizes[1] / 32;
    int total = V * 40;
    int threads = 128;
    int blocks = (total + threads - 1) / threads;
    bc_kernel<<<blocks, threads>>>(tmpl, proj, (float*)d_out, V);
}